// round 6
// baseline (speedup 1.0000x reference)
#include <cuda_runtime.h>
#include <cstdint>

// MXFP8 E4M3 quantize->dequantize, 32-element blocks along last axis.
// R5: revert to the proven R2 operating point (4 fully-coalesced front-batched
// LDG.128 streams per thread, 8 lanes per MX block, 3x shfl.xor reduce) —
// R3/R4 showed L1tex line-tracking is the binding resource, and coalesced
// 4-line LDGs maximize lines-in-flight per MSHR. Micro-tweaks vs R2:
//   * store each stream immediately after processing (shorter register
//     lifetimes -> fewer regs -> higher occupancy)
//   * block=512 (fewer CTAs, same warp count)
//
// All scales are exact powers of two built by bit manipulation, so every
// multiply matches the reference's fp32 divide bit-for-bit.

static constexpr int EMAX = 8;           // e4m3
static constexpr float MAX_NORM = 448.0f;
static constexpr int ILP = 4;

__device__ __forceinline__ float quant_e4m3(float x, float iscale, float scale) {
    float a = x * iscale;                          // exact (iscale = 2^k)
    uint32_t au = __float_as_uint(a);
    uint32_t ab = au & 0x7fffffffu;                // |a|
    int pe = (int)(ab >> 23) - 127;                // floor(log2|a|), exact for normals
    pe = max(pe, -6);                              // MIN_EXP (denorm region clamp)
    // lshift = 2^(3-pe), inv_lshift = 2^(pe-3); pe in [-6, 8] -> both normal
    float lsh  = __uint_as_float((uint32_t)(130 - pe) << 23);
    float ilsh = __uint_as_float((uint32_t)(124 + pe) << 23);
    // round-half-away-from-zero on magnitude: product is exact, +0.5 rounds once
    float r = floorf(__uint_as_float(ab) * lsh + 0.5f);
    float m = fminf(r * ilsh, MAX_NORM);           // saturate to e4m3 max normal
    float res = m * scale;
    return __uint_as_float(__float_as_uint(res) | (au & 0x80000000u));
}

__device__ __forceinline__ float4 process4(float4 v) {
    float ax = fmaxf(fmaxf(fabsf(v.x), fabsf(v.y)), fmaxf(fabsf(v.z), fabsf(v.w)));
    ax = fmaxf(ax, __shfl_xor_sync(0xffffffffu, ax, 1));
    ax = fmaxf(ax, __shfl_xor_sync(0xffffffffu, ax, 2));
    ax = fmaxf(ax, __shfl_xor_sync(0xffffffffu, ax, 4));

    int e = (int)(__float_as_uint(ax) >> 23);      // ax >= 0, no sign bit
    int se = e - 127 - EMAX;
    se = max(se, -127);
    float scale  = __uint_as_float((uint32_t)(se + 127) << 23);
    float iscale = __uint_as_float((uint32_t)(127 - se) << 23);

    v.x = quant_e4m3(v.x, iscale, scale);
    v.y = quant_e4m3(v.y, iscale, scale);
    v.z = quant_e4m3(v.z, iscale, scale);
    v.w = quant_e4m3(v.w, iscale, scale);
    return v;
}

__global__ void __launch_bounds__(512) mxq_kernel(const float4* __restrict__ in,
                                                  float4* __restrict__ out,
                                                  int stride) {
    int gid = blockIdx.x * blockDim.x + threadIdx.x;

    // Front-batched fully-coalesced independent loads (MLP_p1 = 4, nL=4 each)
    float4 v0 = __ldcs(&in[gid]);
    float4 v1 = __ldcs(&in[gid + stride]);
    float4 v2 = __ldcs(&in[gid + 2 * stride]);
    float4 v3 = __ldcs(&in[gid + 3 * stride]);

    // Process + store each stream as soon as it's ready: registers retire
    // early, keeping reg count low and occupancy high.
    v0 = process4(v0);
    __stcs(&out[gid], v0);
    v1 = process4(v1);
    __stcs(&out[gid + stride], v1);
    v2 = process4(v2);
    __stcs(&out[gid + 2 * stride], v2);
    v3 = process4(v3);
    __stcs(&out[gid + 3 * stride], v3);
}

extern "C" void kernel_launch(void* const* d_in, const int* in_sizes, int n_in,
                              void* d_out, int out_size) {
    const float4* in = (const float4*)d_in[0];
    float4* out = (float4*)d_out;
    int n4 = out_size / 4;                         // 16,777,216 float4s
    int threads = 512;
    int total_threads = n4 / ILP;                  // 4,194,304
    int blocks = total_threads / threads;          // 8192
    mxq_kernel<<<blocks, threads>>>(in, out, total_threads);
}